// round 1
// baseline (speedup 1.0000x reference)
#include <cuda_runtime.h>
#include <math.h>

#define NMAX 262144
#define CNUM 1024
#define DDIM 128
#define BLOCK_T 256
#define WARPS_PER_BLOCK (BLOCK_T / 32)

// Scratch in device globals (no allocations allowed).
__device__ int   g_counts[CNUM];
__device__ int   g_offsets[CNUM];
__device__ int   g_cursor[CNUM];
__device__ int   g_rowidx[NMAX];
__device__ float g_loss_sum;
__device__ float g_nvalid;
__device__ int   g_is64;   // 1 if labels are int64, 0 if int32

// ---------------------------------------------------------------------------
// Kernel 1: zero counters/scalars + detect label dtype.
// If labels are int64 (values < 1024), every odd 32-bit word is 0.
// If int32, odd words are random labels in [0,1024) -> ~always nonzero among 128 probes.
__global__ void k_zero(const unsigned int* __restrict__ labels_words, int n) {
    __shared__ int ok;
    int t = threadIdx.x;
    if (t == 0) ok = 1;
    __syncthreads();
    if (t < CNUM) g_counts[t] = 0;
    if (t < 128) {
        int idx = 2 * t + 1;
        // Safe for either dtype: int32 buffer has n words >= 256; int64 has 2n.
        if (idx < n && labels_words[idx] != 0u) ok = 0;
    }
    __syncthreads();
    if (t == 0) {
        g_is64 = ok;
        g_loss_sum = 0.0f;
        g_nvalid = 0.0f;
    }
}

__device__ __forceinline__ int load_label(const void* labels, int i, int is64) {
    if (is64) return (int)((const long long*)labels)[i];
    return ((const int*)labels)[i];
}

// ---------------------------------------------------------------------------
// Kernel 2: histogram of labels.
__global__ void k_hist(const void* __restrict__ labels, int n) {
    int i = blockIdx.x * blockDim.x + threadIdx.x;
    int is64 = g_is64;
    if (i < n) {
        unsigned int c = (unsigned int)load_label(labels, i, is64);
        if (c < CNUM) atomicAdd(&g_counts[c], 1);
    }
}

// ---------------------------------------------------------------------------
// Kernel 3: exclusive prefix scan over 1024 counts (single block, 1024 thr).
__global__ void k_scan() {
    __shared__ int s[CNUM];
    int t = threadIdx.x;
    int my = g_counts[t];
    s[t] = my;
    __syncthreads();
    for (int off = 1; off < CNUM; off <<= 1) {
        int v = (t >= off) ? s[t - off] : 0;
        __syncthreads();
        s[t] += v;
        __syncthreads();
    }
    int excl = s[t] - my;
    g_offsets[t] = excl;
    g_cursor[t]  = excl;
}

// ---------------------------------------------------------------------------
// Kernel 4: counting-sort scatter of row indices by class.
__global__ void k_scatter(const void* __restrict__ labels, int n) {
    int i = blockIdx.x * blockDim.x + threadIdx.x;
    int is64 = g_is64;
    if (i < n) {
        unsigned int c = (unsigned int)load_label(labels, i, is64);
        if (c < CNUM) {
            int p = atomicAdd(&g_cursor[c], 1);
            g_rowidx[p] = i;
        }
    }
}

// ---------------------------------------------------------------------------
// Kernel 5: per-class accumulation. One block per class; each warp processes
// rows of this class; lanes hold float4 slices of the 128-dim vector so the
// class sum lives entirely in registers (no atomics in the hot loop).
__global__ __launch_bounds__(BLOCK_T) void k_main(const float* __restrict__ emb) {
    int c = blockIdx.x;
    int cnt = g_counts[c];
    __shared__ float sacc[WARPS_PER_BLOCK][DDIM];
    __shared__ float wsum[4];

    int wid  = threadIdx.x >> 5;
    int lane = threadIdx.x & 31;

    float4 acc = make_float4(0.f, 0.f, 0.f, 0.f);
    if (cnt > 0) {
        int start = g_offsets[c];
        for (int j = wid; j < cnt; j += WARPS_PER_BLOCK) {
            int row = __ldg(&g_rowidx[start + j]);
            float4 v = *reinterpret_cast<const float4*>(emb + (size_t)row * DDIM + lane * 4);
            float ss = v.x * v.x + v.y * v.y + v.z * v.z + v.w * v.w;
            #pragma unroll
            for (int o = 16; o; o >>= 1) ss += __shfl_xor_sync(0xffffffffu, ss, o);
            float scale = 1.0f / fmaxf(sqrtf(ss), 1e-12f);
            acc.x += v.x * scale;
            acc.y += v.y * scale;
            acc.z += v.z * scale;
            acc.w += v.w * scale;
        }
    }
    sacc[wid][lane * 4 + 0] = acc.x;
    sacc[wid][lane * 4 + 1] = acc.y;
    sacc[wid][lane * 4 + 2] = acc.z;
    sacc[wid][lane * 4 + 3] = acc.w;
    __syncthreads();

    // Reduce 8 warp partials -> s_d, then sum of squares over d in [0,128).
    float ssq = 0.f;
    if (threadIdx.x < DDIM) {
        float s = 0.f;
        #pragma unroll
        for (int w = 0; w < WARPS_PER_BLOCK; w++) s += sacc[w][threadIdx.x];
        ssq = s * s;
    }
    #pragma unroll
    for (int o = 16; o; o >>= 1) ssq += __shfl_xor_sync(0xffffffffu, ssq, o);
    if (threadIdx.x < DDIM && lane == 0) wsum[wid] = ssq;
    __syncthreads();

    if (threadIdx.x == 0 && cnt >= 2) {
        float tot = wsum[0] + wsum[1] + wsum[2] + wsum[3];
        float norm = sqrtf(tot);
        float per_class = ((float)cnt - norm) / (float)cnt;
        atomicAdd(&g_loss_sum, per_class);
        atomicAdd(&g_nvalid, 1.0f);
    }
}

// ---------------------------------------------------------------------------
// Kernel 6: final scalar.
__global__ void k_final(float* __restrict__ out) {
    float nv = g_nvalid;
    out[0] = (nv > 0.f) ? (g_loss_sum / nv) : 0.f;
}

// ---------------------------------------------------------------------------
extern "C" void kernel_launch(void* const* d_in, const int* in_sizes, int n_in,
                              void* d_out, int out_size) {
    const float* emb    = (const float*)d_in[0];
    const void*  labels = d_in[1];
    int n = in_sizes[1];           // number of samples (labels element count)
    if (n > NMAX) n = NMAX;        // scratch bound (problem shape is fixed)

    int tb = BLOCK_T;
    int gb = (n + tb - 1) / tb;

    k_zero<<<1, 1024>>>((const unsigned int*)labels, n);
    k_hist<<<gb, tb>>>(labels, n);
    k_scan<<<1, CNUM>>>();
    k_scatter<<<gb, tb>>>(labels, n);
    k_main<<<CNUM, BLOCK_T>>>(emb);
    k_final<<<1, 1>>>((float*)d_out);
}

// round 4
// speedup vs baseline: 1.6514x; 1.6514x over previous
#include <cuda_runtime.h>
#include <math.h>

#define NMAX 262144
#define CNUM 1024
#define DDIM 128
#define BLOCK_T 256
#define WARPS_PER_BLOCK (BLOCK_T / 32)

#define SC_T 1024          // scatter/hist block threads
#define SC_ELEMS 2         // elements per thread in scatter
#define SC_CHUNK (SC_T * SC_ELEMS)

// Scratch in device globals (no allocations allowed).
__device__ int   g_counts[CNUM];
__device__ int   g_offsets[CNUM];
__device__ int   g_cursor[CNUM];
__device__ int   g_rowidx[NMAX];
__device__ float g_loss_sum;
__device__ float g_nvalid;
__device__ int   g_is64;   // 1 if labels are int64, 0 if int32

// ---------------------------------------------------------------------------
// Kernel 1: zero counters/scalars + detect label dtype.
// int64 labels < 1024 -> every odd 32-bit word is 0. int32 -> odd words are
// random labels, ~always nonzero among 128 probes.
__global__ void k_zero(const unsigned int* __restrict__ labels_words, int n) {
    __shared__ int ok;
    int t = threadIdx.x;
    if (t == 0) ok = 1;
    __syncthreads();
    if (t < CNUM) g_counts[t] = 0;
    if (t < 128) {
        int idx = 2 * t + 1;
        if (idx < n && labels_words[idx] != 0u) ok = 0;
    }
    __syncthreads();
    if (t == 0) {
        g_is64 = ok;
        g_loss_sum = 0.0f;
        g_nvalid = 0.0f;
    }
}

__device__ __forceinline__ int load_label(const void* labels, int i, int is64) {
    if (is64) return (int)((const long long*)labels)[i];
    return ((const int*)labels)[i];
}

// ---------------------------------------------------------------------------
// Kernel 2: histogram, privatized in shared memory. Grid-stride; one global
// no-return atomic per touched class per block.
__global__ __launch_bounds__(SC_T) void k_hist(const void* __restrict__ labels, int n) {
    __shared__ int h[CNUM];
    int t = threadIdx.x;
    h[t] = 0;
    __syncthreads();
    int is64 = g_is64;
    int stride = gridDim.x * blockDim.x;
    for (int i = blockIdx.x * blockDim.x + t; i < n; i += stride) {
        unsigned int c = (unsigned int)load_label(labels, i, is64);
        if (c < CNUM) atomicAdd(&h[c], 1);
    }
    __syncthreads();
    int v = h[t];
    if (v) atomicAdd(&g_counts[t], v);   // result unused -> compiles to RED
}

// ---------------------------------------------------------------------------
// Kernel 3: exclusive prefix scan over 1024 counts (single block).
__global__ void k_scan() {
    __shared__ int s[CNUM];
    int t = threadIdx.x;
    int my = g_counts[t];
    s[t] = my;
    __syncthreads();
    for (int off = 1; off < CNUM; off <<= 1) {
        int v = (t >= off) ? s[t - off] : 0;
        __syncthreads();
        s[t] += v;
        __syncthreads();
    }
    int excl = s[t] - my;
    g_offsets[t] = excl;
    g_cursor[t]  = excl;
}

// ---------------------------------------------------------------------------
// Kernel 4: blocked counting-sort scatter.
// Phase 1: local ranks via smem atomics. Phase 2: one returning global atomic
// per touched class reserves this block's range. Phase 3: plain stores.
__global__ __launch_bounds__(SC_T) void k_scatter(const void* __restrict__ labels, int n) {
    __shared__ int cur[CNUM];
    __shared__ int base[CNUM];
    int t = threadIdx.x;
    cur[t] = 0;
    __syncthreads();

    int is64 = g_is64;
    int blk0 = blockIdx.x * SC_CHUNK;

    int myc[SC_ELEMS], myrank[SC_ELEMS], myi[SC_ELEMS];
    #pragma unroll
    for (int e = 0; e < SC_ELEMS; e++) {
        int i = blk0 + e * SC_T + t;
        myi[e] = i;
        myc[e] = -1;
        if (i < n) {
            unsigned int c = (unsigned int)load_label(labels, i, is64);
            if (c < CNUM) {
                myc[e] = (int)c;
                myrank[e] = atomicAdd(&cur[c], 1);
            }
        }
    }
    __syncthreads();

    int cnt = cur[t];
    if (cnt > 0) base[t] = atomicAdd(&g_cursor[t], cnt);
    __syncthreads();

    #pragma unroll
    for (int e = 0; e < SC_ELEMS; e++) {
        if (myc[e] >= 0) g_rowidx[base[myc[e]] + myrank[e]] = myi[e];
    }
}

// ---------------------------------------------------------------------------
// Kernel 5: per-class accumulation. One block per class; each warp gathers
// rows (512B coalesced float4 per lane), normalizes via shfl reduce, keeps
// the class sum in registers. x2 unroll + next-index prefetch for MLP.
__global__ __launch_bounds__(BLOCK_T) void k_main(const float* __restrict__ emb) {
    int c = blockIdx.x;
    int cnt = g_counts[c];
    __shared__ float sacc[WARPS_PER_BLOCK][DDIM];
    __shared__ float wsum[4];

    int wid  = threadIdx.x >> 5;
    int lane = threadIdx.x & 31;

    float4 acc = make_float4(0.f, 0.f, 0.f, 0.f);
    if (cnt > 0) {
        int start = g_offsets[c];
        int j = wid;
        int row0 = 0, row1 = 0;
        if (j < cnt)                    row0 = __ldg(&g_rowidx[start + j]);
        if (j + WARPS_PER_BLOCK < cnt)  row1 = __ldg(&g_rowidx[start + j + WARPS_PER_BLOCK]);
        for (; j + WARPS_PER_BLOCK < cnt; j += 2 * WARPS_PER_BLOCK) {
            // prefetch next pair of indices before issuing this pair's gathers
            int nj = j + 2 * WARPS_PER_BLOCK;
            int nrow0 = (nj < cnt)                   ? __ldg(&g_rowidx[start + nj]) : 0;
            int nrow1 = (nj + WARPS_PER_BLOCK < cnt) ? __ldg(&g_rowidx[start + nj + WARPS_PER_BLOCK]) : 0;

            float4 v0 = *reinterpret_cast<const float4*>(emb + (size_t)row0 * DDIM + lane * 4);
            float4 v1 = *reinterpret_cast<const float4*>(emb + (size_t)row1 * DDIM + lane * 4);
            float s0 = v0.x * v0.x + v0.y * v0.y + v0.z * v0.z + v0.w * v0.w;
            float s1 = v1.x * v1.x + v1.y * v1.y + v1.z * v1.z + v1.w * v1.w;
            #pragma unroll
            for (int o = 16; o; o >>= 1) {
                s0 += __shfl_xor_sync(0xffffffffu, s0, o);
                s1 += __shfl_xor_sync(0xffffffffu, s1, o);
            }
            float sc0 = rsqrtf(fmaxf(s0, 1e-24f));
            float sc1 = rsqrtf(fmaxf(s1, 1e-24f));
            acc.x += v0.x * sc0 + v1.x * sc1;
            acc.y += v0.y * sc0 + v1.y * sc1;
            acc.z += v0.z * sc0 + v1.z * sc1;
            acc.w += v0.w * sc0 + v1.w * sc1;
            row0 = nrow0; row1 = nrow1;
        }
        // Tail: at most one iteration (j < cnt <= j + WARPS_PER_BLOCK). Plain load.
        for (; j < cnt; j += WARPS_PER_BLOCK) {
            int row = __ldg(&g_rowidx[start + j]);
            float4 v = *reinterpret_cast<const float4*>(emb + (size_t)row * DDIM + lane * 4);
            float ss = v.x * v.x + v.y * v.y + v.z * v.z + v.w * v.w;
            #pragma unroll
            for (int o = 16; o; o >>= 1) ss += __shfl_xor_sync(0xffffffffu, ss, o);
            float scale = rsqrtf(fmaxf(ss, 1e-24f));
            acc.x += v.x * scale;
            acc.y += v.y * scale;
            acc.z += v.z * scale;
            acc.w += v.w * scale;
        }
    }
    sacc[wid][lane * 4 + 0] = acc.x;
    sacc[wid][lane * 4 + 1] = acc.y;
    sacc[wid][lane * 4 + 2] = acc.z;
    sacc[wid][lane * 4 + 3] = acc.w;
    __syncthreads();

    // Reduce 8 warp partials -> s_d, then ssq over d in [0,128).
    float ssq = 0.f;
    if (threadIdx.x < DDIM) {
        float s = 0.f;
        #pragma unroll
        for (int w = 0; w < WARPS_PER_BLOCK; w++) s += sacc[w][threadIdx.x];
        ssq = s * s;
    }
    #pragma unroll
    for (int o = 16; o; o >>= 1) ssq += __shfl_xor_sync(0xffffffffu, ssq, o);
    if (threadIdx.x < DDIM && lane == 0) wsum[wid] = ssq;
    __syncthreads();

    if (threadIdx.x == 0 && cnt >= 2) {
        float tot = wsum[0] + wsum[1] + wsum[2] + wsum[3];
        float norm = sqrtf(tot);
        float per_class = ((float)cnt - norm) / (float)cnt;
        atomicAdd(&g_loss_sum, per_class);
        atomicAdd(&g_nvalid, 1.0f);
    }
}

// ---------------------------------------------------------------------------
// Kernel 6: final scalar.
__global__ void k_final(float* __restrict__ out) {
    float nv = g_nvalid;
    out[0] = (nv > 0.f) ? (g_loss_sum / nv) : 0.f;
}

// ---------------------------------------------------------------------------
extern "C" void kernel_launch(void* const* d_in, const int* in_sizes, int n_in,
                              void* d_out, int out_size) {
    const float* emb    = (const float*)d_in[0];
    const void*  labels = d_in[1];
    int n = in_sizes[1];
    if (n > NMAX) n = NMAX;

    int hist_blocks = 256;
    int sc_blocks = (n + SC_CHUNK - 1) / SC_CHUNK;

    k_zero<<<1, 1024>>>((const unsigned int*)labels, n);
    k_hist<<<hist_blocks, SC_T>>>(labels, n);
    k_scan<<<1, CNUM>>>();
    k_scatter<<<sc_blocks, SC_T>>>(labels, n);
    k_main<<<CNUM, BLOCK_T>>>(emb);
    k_final<<<1, 1>>>((float*)d_out);
}